// round 2
// baseline (speedup 1.0000x reference)
#include <cuda_runtime.h>
#include <cuda_fp16.h>
#include <stdint.h>

// ---------------- problem constants ----------------
#define DD 64
#define HH 64
#define BBATCH 128
#define NSLICE (BBATCH*HH)          // 8192 (b,h) slices
#define SLICE_ELEMS (DD*DD)         // 4096
#define N_BHDD (NSLICE*SLICE_ELEMS) // 33554432

// output layout: [memory_output | scores | new_memory_key | new_memory_norm]
#define OFF_SCORES ((long)N_BHDD)
#define OFF_MK     ((long)2*N_BHDD)
#define OFF_NORM   ((long)2*N_BHDD + SLICE_ELEMS)

// ---------------- device scratch (static, no allocs) ----------------
__device__ __half g_mkT [HH*SLICE_ELEMS];  // A1[m][n] = fp16(MK[h][n][m])
__device__ __half g_mvHi[HH*SLICE_ELEMS];  // fp16 hi of MV[h][n][m]
__device__ __half g_mvLo[HH*SLICE_ELEMS];  // fp16 lo of MV
__device__ float  g_invn[DD];

#define RBLOCKS 512
#define SLICES_PER_BLK 16
__device__ float g_scrK[RBLOCKS*SLICE_ELEMS];
__device__ float g_scrV[RBLOCKS*SLICE_ELEMS];
__device__ float g_scrB[RBLOCKS*DD];
__device__ float g_meanK[SLICE_ELEMS];
__device__ float g_meanV[SLICE_ELEMS];
__device__ float g_bind[DD];

// ---------------- prep: operand preprocessing ----------------
__global__ void prep_kernel(const float* __restrict__ mk,
                            const float* __restrict__ mv,
                            const float* __restrict__ mnorm) {
    int h = blockIdx.x, t = threadIdx.x;
    const float* mkh = mk + h*SLICE_ELEMS;
    const float* mvh = mv + h*SLICE_ELEMS;
#pragma unroll
    for (int j = 0; j < 16; j++) {
        int e = t + 256*j;
        int n = e >> 6, m = e & 63;
        g_mkT[h*SLICE_ELEMS + m*DD + n] = __float2half_rn(mkh[e]);
        float v  = mvh[e];
        __half hi = __float2half_rn(v);
        g_mvHi[h*SLICE_ELEMS + e] = hi;
        g_mvLo[h*SLICE_ELEMS + e] = __float2half_rn(v - __half2float(hi));
    }
    if (h == 0 && t < DD) g_invn[t] = 1.0f / (mnorm[t] + 1e-6f);
}

// ---------------- reduction pass over key/value (deterministic) ----------------
__global__ __launch_bounds__(256) void reduce1_kernel(const float* __restrict__ key,
                                                      const float* __restrict__ val) {
    __shared__ float ks[DD*65];
    __shared__ float vs[DD*65];
    __shared__ float S[DD];
    int t = threadIdx.x, blk = blockIdx.x;
    float accK[16], accV[16];
#pragma unroll
    for (int j = 0; j < 16; j++) { accK[j] = 0.f; accV[j] = 0.f; }
    float bindAcc = 0.f;

    for (int i = 0; i < SLICES_PER_BLK; i++) {
        int base = (blk*SLICES_PER_BLK + i) * SLICE_ELEMS;
#pragma unroll
        for (int j = 0; j < 16; j++) {
            int e = t + 256*j;
            float kr = key[base + e];
            float vr = val[base + e];
            accK[j] += kr; accV[j] += vr;
            int n = e >> 6, d = e & 63;
            ks[n*65 + d] = __half2float(__float2half_rn(kr));  // fp16-rounded, fp32 math
            vs[n*65 + d] = __half2float(__float2half_rn(vr));
        }
        __syncthreads();
        if (t < DD) {                         // S[d] = sum_n k16[n][d]
            float s = 0.f;
#pragma unroll
            for (int n = 0; n < DD; n++) s += ks[n*65 + t];
            S[t] = s;
        }
        __syncthreads();
        if (t < DD) {                         // bind[m] += sum_d S[d]*v16[m][d]
            float bs = 0.f;
#pragma unroll
            for (int d = 0; d < DD; d++) bs += S[d] * vs[t*65 + d];
            bindAcc += bs;
        }
        __syncthreads();
    }
#pragma unroll
    for (int j = 0; j < 16; j++) {
        int e = t + 256*j;
        g_scrK[blk*SLICE_ELEMS + e] = accK[j];
        g_scrV[blk*SLICE_ELEMS + e] = accV[j];
    }
    if (t < DD) g_scrB[blk*DD + t] = bindAcc;
}

__global__ void reduce2_kernel() {
    int blk = blockIdx.x, t = threadIdx.x;
    if (blk < 16) {
        int e = blk*256 + t;
        float sk = 0.f, sv = 0.f;
        for (int p = 0; p < RBLOCKS; p++) {
            sk += g_scrK[p*SLICE_ELEMS + e];
            sv += g_scrV[p*SLICE_ELEMS + e];
        }
        g_meanK[e] = sk * (1.0f / NSLICE);
        g_meanV[e] = sv * (1.0f / NSLICE);
    } else if (t < DD) {
        float sb = 0.f;
        for (int p = 0; p < RBLOCKS; p++) sb += g_scrB[p*DD + t];
        g_bind[t] = sb * (1.0f / ((float)NSLICE * DD));
    }
}

__global__ void finalize_kernel(const float* __restrict__ mnorm,
                                const float* __restrict__ crate,
                                float* __restrict__ out) {
    __shared__ float sn[DD];
    __shared__ float meanv;
    int t = threadIdx.x;  // 64 threads
    float s2 = 0.f;
#pragma unroll
    for (int d = 0; d < DD; d++) { float x = g_meanK[t*DD + d]; s2 += x*x; }
    float nn = mnorm[t] + sqrtf(s2);
    sn[t] = nn;
    __syncthreads();
    if (t == 0) {
        float s = 0.f;
        for (int i = 0; i < DD; i++) s += sn[i];
        meanv = s * (1.0f / DD);
    }
    __syncthreads();
    float factor = (meanv > 0.9f) ? crate[t] : 1.0f;
    out[OFF_NORM + t] = nn * factor;
    float bf = g_bind[t] * factor;
    for (int d = 0; d < DD; d++)
        out[OFF_MK + t*DD + d] = bf * g_meanV[t*DD + d];
}

// ---------------- main retrieve kernel: 3 HMMA GEMMs per (b,h) ----------------
#define SA 72     // halves per row, A tiles  -> (4g+t)%32 banks, conflict-free
#define SBT 136   // halves per row, Bt tiles -> (4g+t)%32 banks, conflict-free

__global__ __launch_bounds__(256) void main_kernel(const float* __restrict__ q,
                                                   float* __restrict__ out) {
    __shared__ __half sA1[DD*SA];
    __shared__ __half sAh[DD*SA];
    __shared__ __half sAl[DD*SA];
    __shared__ __half sBt[DD*SBT];   // q16^T for GEMM1, then P16^T for GEMM2
    __shared__ float  sInv[DD];

    int t = threadIdx.x;
    int s = blockIdx.x;           // s = b*64 + h
    int h = s & (HH-1);

    // ---- cooperative loads ----
    {
        const uint32_t* gA1 = (const uint32_t*)(g_mkT  + h*SLICE_ELEMS);
        const uint32_t* gAh = (const uint32_t*)(g_mvHi + h*SLICE_ELEMS);
        const uint32_t* gAl = (const uint32_t*)(g_mvLo + h*SLICE_ELEMS);
        uint32_t* s1 = (uint32_t*)sA1;
        uint32_t* s2 = (uint32_t*)sAh;
        uint32_t* s3 = (uint32_t*)sAl;
#pragma unroll
        for (int j = 0; j < 8; j++) {
            int w = t + 256*j;              // 2048 words per tile; 32 words/row
            int sidx = (w >> 5) * (SA/2) + (w & 31);
            s1[sidx] = gA1[w];
            s2[sidx] = gAh[w];
            s3[sidx] = gAl[w];
        }
        const float* qs = q + (long)s*SLICE_ELEMS;
#pragma unroll
        for (int j = 0; j < 16; j++) {
            int e = t + 256*j;
            int n = e >> 6, d = e & 63;
            sBt[d*SBT + n] = __float2half_rn(qs[e]);   // transpose: Bt[d][n]
        }
        if (t < DD) sInv[t] = g_invn[t];
    }
    __syncthreads();

    int lane = t & 31, w = t >> 5;
    int g  = lane >> 2, tq = lane & 3;
    int mrow0 = (w & 3) * 16;
    int ncol0 = (w >> 2) * 32;

    float c[4][4];
#pragma unroll
    for (int j = 0; j < 4; j++) { c[j][0]=0.f; c[j][1]=0.f; c[j][2]=0.f; c[j][3]=0.f; }

    // ---- GEMM1: P[m][d] = sum_n mkT16[m][n] * q16[n][d] ----
#pragma unroll
    for (int kk = 0; kk < 4; kk++) {
        int ko = kk * 16;
        uint32_t a0 = *(const uint32_t*)&sA1[(mrow0+g  )*SA + ko + 2*tq    ];
        uint32_t a1 = *(const uint32_t*)&sA1[(mrow0+g+8)*SA + ko + 2*tq    ];
        uint32_t a2 = *(const uint32_t*)&sA1[(mrow0+g  )*SA + ko + 2*tq + 8];
        uint32_t a3 = *(const uint32_t*)&sA1[(mrow0+g+8)*SA + ko + 2*tq + 8];
#pragma unroll
        for (int j = 0; j < 4; j++) {
            int col = ncol0 + 8*j + g;
            uint32_t b0 = *(const uint32_t*)&sBt[col*SBT + ko + 2*tq    ];
            uint32_t b1 = *(const uint32_t*)&sBt[col*SBT + ko + 2*tq + 8];
            asm volatile("mma.sync.aligned.m16n8k16.row.col.f32.f16.f16.f32 "
                "{%0,%1,%2,%3},{%4,%5,%6,%7},{%8,%9},{%0,%1,%2,%3};\n"
                : "+f"(c[j][0]), "+f"(c[j][1]), "+f"(c[j][2]), "+f"(c[j][3])
                : "r"(a0), "r"(a1), "r"(a2), "r"(a3), "r"(b0), "r"(b1));
        }
    }
    __syncthreads();   // everyone done reading q16 from sBt

    // ---- round P -> fp16 (emulating reference fp16 einsum output),
    //      write scores = fp16(P)*inv(d), stage P16^T into sBt ----
    float* outS = out + OFF_SCORES + (long)s*SLICE_ELEMS;
#pragma unroll
    for (int j = 0; j < 4; j++) {
        int col = ncol0 + 8*j + 2*tq;
        int r1 = mrow0 + g, r2 = r1 + 8;
        __half h00 = __float2half_rn(c[j][0]);
        __half h01 = __float2half_rn(c[j][1]);
        __half h10 = __float2half_rn(c[j][2]);
        __half h11 = __float2half_rn(c[j][3]);
        sBt[ col   *SBT + r1] = h00;
        sBt[(col+1)*SBT + r1] = h01;
        sBt[ col   *SBT + r2] = h10;
        sBt[(col+1)*SBT + r2] = h11;
        float i0 = sInv[col], i1 = sInv[col+1];
        *(float2*)&outS[r1*DD + col] = make_float2(__half2float(h00)*i0, __half2float(h01)*i1);
        *(float2*)&outS[r2*DD + col] = make_float2(__half2float(h10)*i0, __half2float(h11)*i1);
    }
    __syncthreads();

    // ---- GEMM2: O[n][d] = inv(d) * sum_m (MVhi+MVlo)[n][m] * P16[m][d] ----
#pragma unroll
    for (int j = 0; j < 4; j++) { c[j][0]=0.f; c[j][1]=0.f; c[j][2]=0.f; c[j][3]=0.f; }
#pragma unroll
    for (int kk = 0; kk < 4; kk++) {
        int ko = kk * 16;
        uint32_t b0[4], b1[4];
#pragma unroll
        for (int j = 0; j < 4; j++) {
            int col = ncol0 + 8*j + g;
            b0[j] = *(const uint32_t*)&sBt[col*SBT + ko + 2*tq    ];
            b1[j] = *(const uint32_t*)&sBt[col*SBT + ko + 2*tq + 8];
        }
        uint32_t a0 = *(const uint32_t*)&sAh[(mrow0+g  )*SA + ko + 2*tq    ];
        uint32_t a1 = *(const uint32_t*)&sAh[(mrow0+g+8)*SA + ko + 2*tq    ];
        uint32_t a2 = *(const uint32_t*)&sAh[(mrow0+g  )*SA + ko + 2*tq + 8];
        uint32_t a3 = *(const uint32_t*)&sAh[(mrow0+g+8)*SA + ko + 2*tq + 8];
#pragma unroll
        for (int j = 0; j < 4; j++) {
            asm volatile("mma.sync.aligned.m16n8k16.row.col.f32.f16.f16.f32 "
                "{%0,%1,%2,%3},{%4,%5,%6,%7},{%8,%9},{%0,%1,%2,%3};\n"
                : "+f"(c[j][0]), "+f"(c[j][1]), "+f"(c[j][2]), "+f"(c[j][3])
                : "r"(a0), "r"(a1), "r"(a2), "r"(a3), "r"(b0[j]), "r"(b1[j]));
        }
        uint32_t l0 = *(const uint32_t*)&sAl[(mrow0+g  )*SA + ko + 2*tq    ];
        uint32_t l1 = *(const uint32_t*)&sAl[(mrow0+g+8)*SA + ko + 2*tq    ];
        uint32_t l2 = *(const uint32_t*)&sAl[(mrow0+g  )*SA + ko + 2*tq + 8];
        uint32_t l3 = *(const uint32_t*)&sAl[(mrow0+g+8)*SA + ko + 2*tq + 8];
#pragma unroll
        for (int j = 0; j < 4; j++) {
            asm volatile("mma.sync.aligned.m16n8k16.row.col.f32.f16.f16.f32 "
                "{%0,%1,%2,%3},{%4,%5,%6,%7},{%8,%9},{%0,%1,%2,%3};\n"
                : "+f"(c[j][0]), "+f"(c[j][1]), "+f"(c[j][2]), "+f"(c[j][3])
                : "r"(l0), "r"(l1), "r"(l2), "r"(l3), "r"(b0[j]), "r"(b1[j]));
        }
    }

    float* outO = out + (long)s*SLICE_ELEMS;
#pragma unroll
    for (int j = 0; j < 4; j++) {
        int col = ncol0 + 8*j + 2*tq;
        int r1 = mrow0 + g, r2 = r1 + 8;
        float i0 = sInv[col], i1 = sInv[col+1];
        *(float2*)&outO[r1*DD + col] = make_float2(c[j][0]*i0, c[j][1]*i1);
        *(float2*)&outO[r2*DD + col] = make_float2(c[j][2]*i0, c[j][3]*i1);
    }
}

// ---------------- launch ----------------
extern "C" void kernel_launch(void* const* d_in, const int* in_sizes, int n_in,
                              void* d_out, int out_size) {
    const float* q     = (const float*)d_in[0];
    const float* key   = (const float*)d_in[1];
    const float* val   = (const float*)d_in[2];
    const float* mk    = (const float*)d_in[3];
    const float* mnorm = (const float*)d_in[4];
    const float* mv    = (const float*)d_in[5];
    const float* cr    = (const float*)d_in[6];
    float* out = (float*)d_out;

    prep_kernel   <<<HH, 256>>>(mk, mv, mnorm);
    reduce1_kernel<<<RBLOCKS, 256>>>(key, val);
    reduce2_kernel<<<17, 256>>>();
    finalize_kernel<<<1, 64>>>(mnorm, cr, out);
    main_kernel   <<<NSLICE, 256>>>(q, out);
}

// round 3
// speedup vs baseline: 1.2807x; 1.2807x over previous
#include <cuda_runtime.h>
#include <cuda_fp16.h>
#include <stdint.h>

// ---------------- problem constants ----------------
#define DD 64
#define HH 64
#define BBATCH 128
#define NSLICE (BBATCH*HH)          // 8192 (b,h) slices
#define SLICE_ELEMS (DD*DD)         // 4096
#define N_BHDD (NSLICE*SLICE_ELEMS) // 33554432

// output layout: [memory_output | scores | new_memory_key | new_memory_norm]
#define OFF_SCORES ((long)N_BHDD)
#define OFF_MK     ((long)2*N_BHDD)
#define OFF_NORM   ((long)2*N_BHDD + SLICE_ELEMS)

// ---------------- device scratch (static, no allocs) ----------------
__device__ __half g_mkT [HH*SLICE_ELEMS];  // A1[m][n] = fp16(MK[h][n][m])
__device__ __half g_mvHi[HH*SLICE_ELEMS];  // fp16 hi of MV[h][n][m]
__device__ __half g_mvLo[HH*SLICE_ELEMS];  // fp16 lo of MV
__device__ float  g_invn[DD];

#define R1BLOCKS 1024
#define R1SLICES 8
__device__ float g_scrK[R1BLOCKS*SLICE_ELEMS];
__device__ float g_scrV[R1BLOCKS*SLICE_ELEMS];
__device__ float g_scrB[R1BLOCKS*DD];
__device__ float g_meanK[SLICE_ELEMS];
__device__ float g_meanV[SLICE_ELEMS];
__device__ float g_bind[DD];

// fp16 round-trip (pairwise, 2 conv instrs per 2 floats)
__device__ __forceinline__ float4 r16(float4 a) {
    __half2 h1 = __floats2half2_rn(a.x, a.y);
    __half2 h2 = __floats2half2_rn(a.z, a.w);
    float2 f1 = __half22float2(h1);
    float2 f2 = __half22float2(h2);
    return make_float4(f1.x, f1.y, f2.x, f2.y);
}

// ---------------- prep: operand preprocessing ----------------
__global__ __launch_bounds__(256) void prep_kernel(const float* __restrict__ mk,
                                                   const float* __restrict__ mv,
                                                   const float* __restrict__ mnorm) {
    int h = blockIdx.x, t = threadIdx.x;
    __shared__ float sm[DD*65];
    const float* mkh = mk + h*SLICE_ELEMS;
    const float* mvh = mv + h*SLICE_ELEMS;
#pragma unroll
    for (int j = 0; j < 16; j++) {
        int e = t + 256*j;
        int n = e >> 6, m = e & 63;
        sm[m*65 + n] = mkh[e];                 // staged transpose, pad-65 conflict-free
        float v  = mvh[e];
        __half hi = __float2half_rn(v);
        g_mvHi[h*SLICE_ELEMS + e] = hi;
        g_mvLo[h*SLICE_ELEMS + e] = __float2half_rn(v - __half2float(hi));
    }
    __syncthreads();
#pragma unroll
    for (int j = 0; j < 16; j++) {
        int e = t + 256*j;                     // e = m*64 + n (output row-major)
        int m = e >> 6, n = e & 63;
        g_mkT[h*SLICE_ELEMS + e] = __float2half_rn(sm[m*65 + n]);  // coalesced write
    }
    if (h == 0 && t < DD) g_invn[t] = 1.0f / (mnorm[t] + 1e-6f);
}

// ---------------- reduction pass 1: all-thread parallel, float4 ----------------
__global__ __launch_bounds__(256) void reduce1_kernel(const float* __restrict__ key,
                                                      const float* __restrict__ val) {
    __shared__ float Spart[8][DD];   // per-warp partial S[d]
    __shared__ float Sfull[DD];
    int t = threadIdx.x;
    int l = t & 31, w = t >> 5;
    int dq = t & 15;         // d-chunk: d = 4*dq .. 4*dq+3
    int nb = t >> 4;         // row base: n = nb + 16*jj

    float4 accK[4], accV[4];
    float bindAcc[4];
#pragma unroll
    for (int j = 0; j < 4; j++) {
        accK[j] = make_float4(0.f,0.f,0.f,0.f);
        accV[j] = make_float4(0.f,0.f,0.f,0.f);
        bindAcc[j] = 0.f;
    }

    for (int i = 0; i < R1SLICES; i++) {
        int sl = blockIdx.x*R1SLICES + i;
        const float4* k4p = (const float4*)(key + (long)sl*SLICE_ELEMS);
        const float4* v4p = (const float4*)(val + (long)sl*SLICE_ELEMS);
        float4 k4[4], v4[4];
#pragma unroll
        for (int jj = 0; jj < 4; jj++) {
            int e4 = t + 256*jj;
            k4[jj] = k4p[e4];
            v4[jj] = v4p[e4];
        }
#pragma unroll
        for (int jj = 0; jj < 4; jj++) {
            accK[jj].x += k4[jj].x; accK[jj].y += k4[jj].y;
            accK[jj].z += k4[jj].z; accK[jj].w += k4[jj].w;
            accV[jj].x += v4[jj].x; accV[jj].y += v4[jj].y;
            accV[jj].z += v4[jj].z; accV[jj].w += v4[jj].w;
            k4[jj] = r16(k4[jj]);
            v4[jj] = r16(v4[jj]);
        }
        // partial S[d] over this thread's 4 rows
        float4 ps;
        ps.x = k4[0].x + k4[1].x + k4[2].x + k4[3].x;
        ps.y = k4[0].y + k4[1].y + k4[2].y + k4[3].y;
        ps.z = k4[0].z + k4[1].z + k4[2].z + k4[3].z;
        ps.w = k4[0].w + k4[1].w + k4[2].w + k4[3].w;
        // combine the two nb's in this warp
        ps.x += __shfl_xor_sync(0xffffffffu, ps.x, 16);
        ps.y += __shfl_xor_sync(0xffffffffu, ps.y, 16);
        ps.z += __shfl_xor_sync(0xffffffffu, ps.z, 16);
        ps.w += __shfl_xor_sync(0xffffffffu, ps.w, 16);
        if (l < 16) *(float4*)&Spart[w][dq*4] = ps;
        __syncthreads();
        if (t < DD) {
            float s = Spart[0][t] + Spart[1][t] + Spart[2][t] + Spart[3][t]
                    + Spart[4][t] + Spart[5][t] + Spart[6][t] + Spart[7][t];
            Sfull[t] = s;
        }
        __syncthreads();
        float4 s4 = *(const float4*)&Sfull[dq*4];
#pragma unroll
        for (int jj = 0; jj < 4; jj++) {
            float pb = v4[jj].x*s4.x + v4[jj].y*s4.y + v4[jj].z*s4.z + v4[jj].w*s4.w;
            pb += __shfl_xor_sync(0xffffffffu, pb, 1);
            pb += __shfl_xor_sync(0xffffffffu, pb, 2);
            pb += __shfl_xor_sync(0xffffffffu, pb, 4);
            pb += __shfl_xor_sync(0xffffffffu, pb, 8);
            bindAcc[jj] += pb;
        }
        __syncthreads();   // Sfull/Spart reuse next iteration
    }
    float4* oK = (float4*)(g_scrK + blockIdx.x*SLICE_ELEMS);
    float4* oV = (float4*)(g_scrV + blockIdx.x*SLICE_ELEMS);
#pragma unroll
    for (int jj = 0; jj < 4; jj++) {
        int e4 = t + 256*jj;
        oK[e4] = accK[jj];
        oV[e4] = accV[jj];
    }
    if (dq == 0) {
#pragma unroll
        for (int jj = 0; jj < 4; jj++)
            g_scrB[blockIdx.x*DD + nb + 16*jj] = bindAcc[jj];
    }
}

// ---------------- reduction pass 2 ----------------
__global__ __launch_bounds__(256) void reduce2_kernel() {
    int blk = blockIdx.x, t = threadIdx.x;
    if (blk < 16) {                // meanK
        int e = blk*256 + t;
        float s = 0.f;
#pragma unroll 8
        for (int p = 0; p < R1BLOCKS; p++) s += g_scrK[p*SLICE_ELEMS + e];
        g_meanK[e] = s * (1.0f / NSLICE);
    } else if (blk < 32) {         // meanV
        int e = (blk-16)*256 + t;
        float s = 0.f;
#pragma unroll 8
        for (int p = 0; p < R1BLOCKS; p++) s += g_scrV[p*SLICE_ELEMS + e];
        g_meanV[e] = s * (1.0f / NSLICE);
    } else {                       // bind
        __shared__ float bb[4][DD];
        int n = t & 63, pq = t >> 6;
        float s = 0.f;
        for (int p = pq; p < R1BLOCKS; p += 4) s += g_scrB[p*DD + n];
        bb[pq][n] = s;
        __syncthreads();
        if (t < DD)
            g_bind[t] = (bb[0][t] + bb[1][t] + bb[2][t] + bb[3][t])
                        * (1.0f / ((float)NSLICE * DD));
    }
}

// ---------------- finalize: norms, factor, new_memory_key ----------------
__global__ __launch_bounds__(256) void finalize_kernel(const float* __restrict__ mnorm,
                                                       const float* __restrict__ crate,
                                                       float* __restrict__ out) {
    __shared__ float nrm[DD];
    __shared__ float bfs[DD];
    __shared__ float meanv;
    int t = threadIdx.x;
    int m = t >> 2, q = t & 3;                  // 4 threads per row
    float s2 = 0.f;
#pragma unroll
    for (int i = 0; i < 4; i++) {
        float4 x = *(const float4*)&g_meanK[m*DD + q*16 + i*4];
        s2 += x.x*x.x + x.y*x.y + x.z*x.z + x.w*x.w;
    }
    s2 += __shfl_xor_sync(0xffffffffu, s2, 1);
    s2 += __shfl_xor_sync(0xffffffffu, s2, 2);
    if (q == 0) nrm[m] = mnorm[m] + sqrtf(s2);
    __syncthreads();
    if (t == 0) {
        float s = 0.f;
        for (int i = 0; i < DD; i++) s += nrm[i];
        meanv = s * (1.0f / DD);
    }
    __syncthreads();
    if (t < DD) {
        float f = (meanv > 0.9f) ? crate[t] : 1.0f;
        out[OFF_NORM + t] = nrm[t] * f;
        bfs[t] = g_bind[t] * f;
    }
    __syncthreads();
    float4* oMK = (float4*)(out + OFF_MK);
#pragma unroll
    for (int j = 0; j < 4; j++) {
        int e4 = t + 256*j;
        int row = e4 >> 4;
        float4 v = *(const float4*)&g_meanV[e4*4];
        float b = bfs[row];
        oMK[e4] = make_float4(b*v.x, b*v.y, b*v.z, b*v.w);
    }
}

// ---------------- main retrieve kernel: 3 HMMA GEMMs per (b,h) ----------------
#define SA 72     // halves per row, A tiles  -> conflict-free
#define SBT 136   // halves per row, Bt tiles -> conflict-free

__global__ __launch_bounds__(256) void main_kernel(const float* __restrict__ q,
                                                   float* __restrict__ out) {
    __shared__ __half sA1[DD*SA];
    __shared__ __half sAh[DD*SA];
    __shared__ __half sAl[DD*SA];
    __shared__ __half sBt[DD*SBT];   // q16^T for GEMM1, then P16^T for GEMM2
    __shared__ float  sInv[DD];

    int t = threadIdx.x;
    int s = blockIdx.x;           // s = b*64 + h
    int h = s & (HH-1);

    // ---- cooperative loads ----
    {
        const uint32_t* gA1 = (const uint32_t*)(g_mkT  + h*SLICE_ELEMS);
        const uint32_t* gAh = (const uint32_t*)(g_mvHi + h*SLICE_ELEMS);
        const uint32_t* gAl = (const uint32_t*)(g_mvLo + h*SLICE_ELEMS);
        uint32_t* s1 = (uint32_t*)sA1;
        uint32_t* s2 = (uint32_t*)sAh;
        uint32_t* s3 = (uint32_t*)sAl;
#pragma unroll
        for (int j = 0; j < 8; j++) {
            int w2 = t + 256*j;              // 2048 words per tile; 32 words/row
            int sidx = (w2 >> 5) * (SA/2) + (w2 & 31);
            s1[sidx] = gA1[w2];
            s2[sidx] = gAh[w2];
            s3[sidx] = gAl[w2];
        }
        const float4* qs4 = (const float4*)(q + (long)s*SLICE_ELEMS);
#pragma unroll
        for (int jj = 0; jj < 4; jj++) {
            int e4 = t + 256*jj;
            float4 qv = qs4[e4];
            int n = e4 >> 4, d0 = (e4 & 15) * 4;
            sBt[(d0+0)*SBT + n] = __float2half_rn(qv.x);
            sBt[(d0+1)*SBT + n] = __float2half_rn(qv.y);
            sBt[(d0+2)*SBT + n] = __float2half_rn(qv.z);
            sBt[(d0+3)*SBT + n] = __float2half_rn(qv.w);
        }
        if (t < DD) sInv[t] = g_invn[t];
    }
    __syncthreads();

    int lane = t & 31, w = t >> 5;
    int g  = lane >> 2, tq = lane & 3;
    int mrow0 = (w & 3) * 16;
    int ncol0 = (w >> 2) * 32;

    float c[4][4];
#pragma unroll
    for (int j = 0; j < 4; j++) { c[j][0]=0.f; c[j][1]=0.f; c[j][2]=0.f; c[j][3]=0.f; }

    // ---- GEMM1: P[m][d] = sum_n mkT16[m][n] * q16[n][d] ----
#pragma unroll
    for (int kk = 0; kk < 4; kk++) {
        int ko = kk * 16;
        uint32_t a0 = *(const uint32_t*)&sA1[(mrow0+g  )*SA + ko + 2*tq    ];
        uint32_t a1 = *(const uint32_t*)&sA1[(mrow0+g+8)*SA + ko + 2*tq    ];
        uint32_t a2 = *(const uint32_t*)&sA1[(mrow0+g  )*SA + ko + 2*tq + 8];
        uint32_t a3 = *(const uint32_t*)&sA1[(mrow0+g+8)*SA + ko + 2*tq + 8];
#pragma unroll
        for (int j = 0; j < 4; j++) {
            int col = ncol0 + 8*j + g;
            uint32_t b0 = *(const uint32_t*)&sBt[col*SBT + ko + 2*tq    ];
            uint32_t b1 = *(const uint32_t*)&sBt[col*SBT + ko + 2*tq + 8];
            asm volatile("mma.sync.aligned.m16n8k16.row.col.f32.f16.f16.f32 "
                "{%0,%1,%2,%3},{%4,%5,%6,%7},{%8,%9},{%0,%1,%2,%3};\n"
                : "+f"(c[j][0]), "+f"(c[j][1]), "+f"(c[j][2]), "+f"(c[j][3])
                : "r"(a0), "r"(a1), "r"(a2), "r"(a3), "r"(b0), "r"(b1));
        }
    }
    __syncthreads();   // everyone done reading q16 from sBt

    // ---- round P -> fp16, write scores = fp16(P)*inv(d), stage P16^T ----
    float* outS = out + OFF_SCORES + (long)s*SLICE_ELEMS;
#pragma unroll
    for (int j = 0; j < 4; j++) {
        int col = ncol0 + 8*j + 2*tq;
        int r1 = mrow0 + g, r2 = r1 + 8;
        __half h00 = __float2half_rn(c[j][0]);
        __half h01 = __float2half_rn(c[j][1]);
        __half h10 = __float2half_rn(c[j][2]);
        __half h11 = __float2half_rn(c[j][3]);
        sBt[ col   *SBT + r1] = h00;
        sBt[(col+1)*SBT + r1] = h01;
        sBt[ col   *SBT + r2] = h10;
        sBt[(col+1)*SBT + r2] = h11;
        float i0 = sInv[col], i1 = sInv[col+1];
        *(float2*)&outS[r1*DD + col] = make_float2(__half2float(h00)*i0, __half2float(h01)*i1);
        *(float2*)&outS[r2*DD + col] = make_float2(__half2float(h10)*i0, __half2float(h11)*i1);
    }
    __syncthreads();

    // ---- GEMM2: O[n][d] = inv(d) * sum_m (MVhi+MVlo)[n][m] * P16[m][d] ----
#pragma unroll
    for (int j = 0; j < 4; j++) { c[j][0]=0.f; c[j][1]=0.f; c[j][2]=0.f; c[j][3]=0.f; }
#pragma unroll
    for (int kk = 0; kk < 4; kk++) {
        int ko = kk * 16;
        uint32_t b0[4], b1[4];
#pragma unroll
        for (int j = 0; j < 4; j++) {
            int col = ncol0 + 8*j + g;
            b0[j] = *(const uint32_t*)&sBt[col*SBT + ko + 2*tq    ];
            b1[j] = *(const uint32_t*)&sBt[col*SBT + ko + 2*tq + 8];
        }
        uint32_t a0 = *(const uint32_t*)&sAh[(mrow0+g  )*SA + ko + 2*tq    ];
        uint32_t a1 = *(const uint32_t*)&sAh[(mrow0+g+8)*SA + ko + 2*tq    ];
        uint32_t a2 = *(const uint32_t*)&sAh[(mrow0+g  )*SA + ko + 2*tq + 8];
        uint32_t a3 = *(const uint32_t*)&sAh[(mrow0+g+8)*SA + ko + 2*tq + 8];
#pragma unroll
        for (int j = 0; j < 4; j++) {
            asm volatile("mma.sync.aligned.m16n8k16.row.col.f32.f16.f16.f32 "
                "{%0,%1,%2,%3},{%4,%5,%6,%7},{%8,%9},{%0,%1,%2,%3};\n"
                : "+f"(c[j][0]), "+f"(c[j][1]), "+f"(c[j][2]), "+f"(c[j][3])
                : "r"(a0), "r"(a1), "r"(a2), "r"(a3), "r"(b0[j]), "r"(b1[j]));
        }
        uint32_t l0 = *(const uint32_t*)&sAl[(mrow0+g  )*SA + ko + 2*tq    ];
        uint32_t l1 = *(const uint32_t*)&sAl[(mrow0+g+8)*SA + ko + 2*tq    ];
        uint32_t l2 = *(const uint32_t*)&sAl[(mrow0+g  )*SA + ko + 2*tq + 8];
        uint32_t l3 = *(const uint32_t*)&sAl[(mrow0+g+8)*SA + ko + 2*tq + 8];
#pragma unroll
        for (int j = 0; j < 4; j++) {
            asm volatile("mma.sync.aligned.m16n8k16.row.col.f32.f16.f16.f32 "
                "{%0,%1,%2,%3},{%4,%5,%6,%7},{%8,%9},{%0,%1,%2,%3};\n"
                : "+f"(c[j][0]), "+f"(c[j][1]), "+f"(c[j][2]), "+f"(c[j][3])
                : "r"(l0), "r"(l1), "r"(l2), "r"(l3), "r"(b0[j]), "r"(b1[j]));
        }
    }

    float* outO = out + (long)s*SLICE_ELEMS;
#pragma unroll
    for (int j = 0; j < 4; j++) {
        int col = ncol0 + 8*j + 2*tq;
        int r1 = mrow0 + g, r2 = r1 + 8;
        float i0 = sInv[col], i1 = sInv[col+1];
        *(float2*)&outO[r1*DD + col] = make_float2(c[j][0]*i0, c[j][1]*i1);
        *(float2*)&outO[r2*DD + col] = make_float2(c[j][2]*i0, c[j][3]*i1);
    }
}

// ---------------- launch ----------------
extern "C" void kernel_launch(void* const* d_in, const int* in_sizes, int n_in,
                              void* d_out, int out_size) {
    const float* q     = (const float*)d_in[0];
    const float* key   = (const float*)d_in[1];
    const float* val   = (const float*)d_in[2];
    const float* mk    = (const float*)d_in[3];
    const float* mnorm = (const float*)d_in[4];
    const float* mv    = (const float*)d_in[5];
    const float* cr    = (const float*)d_in[6];
    float* out = (float*)d_out;

    prep_kernel    <<<HH, 256>>>(mk, mv, mnorm);
    reduce1_kernel <<<R1BLOCKS, 256>>>(key, val);
    reduce2_kernel <<<33, 256>>>();
    main_kernel    <<<NSLICE, 256>>>(q, out);
    finalize_kernel<<<1, 256>>>(mnorm, cr, out);
}